// round 16
// baseline (speedup 1.0000x reference)
#include <cuda_runtime.h>
#include <cuda_fp16.h>
#include <cstdint>

#define Bn 4
#define Cn 256
#define Hn 256
#define On 256
#define Nn 4096

// ---------------- scratch (device globals) ----------------------------------
__device__ __half g_x16[(size_t)Bn*Cn*Nn];   // x fp16 [b][c][n]
__device__ __half g_whi[4 * Cn * Hn];        // W fp16 (Wk,Wq,W1,W3)
__device__ __half g_kt [(size_t)Bn*Nn*Hn];   // k^T [b][n][h]
__device__ __half g_qt [(size_t)Bn*Nn*Hn];   // q^T [b][n][h] (scaled by log2e)
__device__ __half g_v1h[(size_t)Bn*Hn*Nn];   // v1 [b][h][n]
__device__ __half g_v2h[(size_t)Bn*Hn*Nn];   // v2 [b][h][n]
__device__ __half g_vh [(size_t)Bn*On*Nn];   // v  [b][o][n]

// ---------------- helpers ----------------------------------------------------
__device__ __forceinline__ uint32_t smem_u32(const void* p) {
    uint32_t a;
    asm("{ .reg .u64 t; cvta.to.shared.u64 t, %1; cvt.u32.u64 %0, t; }" : "=r"(a) : "l"(p));
    return a;
}
__device__ __forceinline__ uint32_t packh2(__half a, __half b) {
    __half2 h = __halves2half2(a, b);
    return *reinterpret_cast<const uint32_t*>(&h);
}
// pack two f32 -> f16x2 in ONE cvt (lo = first arg)
__device__ __forceinline__ uint32_t pack2(float lo, float hi) {
    uint32_t r;
    asm("cvt.rn.f16x2.f32 %0, %1, %2;" : "=r"(r) : "f"(hi), "f"(lo));
    return r;
}
__device__ __forceinline__ float ex2(float x) {
    float r;
    asm("ex2.approx.f32 %0, %1;" : "=f"(r) : "f"(x));
    return r;
}
__device__ __forceinline__ void ldm4(uint32_t* r, uint32_t addr) {
    asm volatile("ldmatrix.sync.aligned.m8n8.x4.shared.b16 {%0,%1,%2,%3}, [%4];"
                 : "=r"(r[0]), "=r"(r[1]), "=r"(r[2]), "=r"(r[3]) : "r"(addr));
}
__device__ __forceinline__ void ldm4t(uint32_t* r, uint32_t addr) {
    asm volatile("ldmatrix.sync.aligned.m8n8.x4.trans.shared.b16 {%0,%1,%2,%3}, [%4];"
                 : "=r"(r[0]), "=r"(r[1]), "=r"(r[2]), "=r"(r[3]) : "r"(addr));
}
__device__ __forceinline__ void mma16816(float* c, const uint32_t* a, uint32_t b0, uint32_t b1) {
    asm volatile("mma.sync.aligned.m16n8k16.row.col.f32.f16.f16.f32 "
                 "{%0,%1,%2,%3}, {%4,%5,%6,%7}, {%8,%9}, {%0,%1,%2,%3};"
                 : "+f"(c[0]), "+f"(c[1]), "+f"(c[2]), "+f"(c[3])
                 : "r"(a[0]), "r"(a[1]), "r"(a[2]), "r"(a[3]), "r"(b0), "r"(b1));
}
#define CP16(dst, src) \
    asm volatile("cp.async.cg.shared.global [%0], [%1], 16;" :: "r"(dst), "l"(src))
#define CP_COMMIT() asm volatile("cp.async.commit_group;" ::: "memory")
#define CP_WAIT0()  asm volatile("cp.async.wait_group 0;" ::: "memory")
#define CP_WAIT1()  asm volatile("cp.async.wait_group 1;" ::: "memory")

// ---------------------------------------------------------------------------
// Merged prep: blocks [0,4096) convert x fp32->fp16; blocks [4096,5120) weights.
// ---------------------------------------------------------------------------
__global__ __launch_bounds__(256) void prep_kernel(
    const float* __restrict__ x,
    const float* __restrict__ W0, const float* __restrict__ W1,
    const float* __restrict__ W2, const float* __restrict__ W3)
{
    if (blockIdx.x < 4096) {
        size_t q = (size_t)blockIdx.x * 256 + threadIdx.x;
        float4 v = *(const float4*)(x + q * 4);
        uint2 u;
        u.x = packh2(__float2half_rn(v.x), __float2half_rn(v.y));
        u.y = packh2(__float2half_rn(v.z), __float2half_rn(v.w));
        *(uint2*)(g_x16 + q * 4) = u;
    } else {
        int bi = blockIdx.x - 4096;        // 0..1023
        int m  = bi >> 8;                  // 256 blocks per matrix
        int e  = (bi & 255) * 256 + threadIdx.x;
        const float* src = (m == 0) ? W0 : (m == 1) ? W1 : (m == 2) ? W2 : W3;
        g_whi[m * 65536 + e] = __float2half_rn(src[e]);
    }
}

// ---------------------------------------------------------------------------
// HMMA projection, CTA tile 128h x 256n, 512 threads (16 warps, 4/SMSP),
// K chunks of 32, 3-stage cp.async ring, 1 sync/chunk.
// smem per buf: W[128 rows x 80B] (at 0) + X[32 rows x 528B] (at PJ_X)
// ---------------------------------------------------------------------------
#define PJ_X     10240
#define PJ_BUF   27136
#define PJ_SMEM  81408

__device__ __forceinline__ void proj_issue(
    uint32_t sb, int buf, const __half* whi,
    const __half* X, int h0, int n0, int c0, int tid)
{
    uint32_t base = sb + buf * PJ_BUF;
    #pragma unroll
    for (int i = 0; i < 3; i++) {
        int idx = tid + i * 512;
        if (idx < 1024) {
            int r = idx >> 5, c = idx & 31;
            CP16(base + PJ_X + r * 528 + c * 16, X + (size_t)(c0 + r) * Nn + n0 + c * 8);
        } else {
            int i2 = idx - 1024;
            int r = i2 >> 2, c = i2 & 3;
            CP16(base + r * 80 + c * 16, whi + (size_t)(h0 + r) * Cn + c0 + c * 8);
        }
    }
}

// MODE 0 ("N"): out [b][h][n].  MODE 1 ("T"): out [b][n][h].
// DUAL=1: gridDim.z = 8, p = z>>2 selects (A,B) weight/bias/out/scale sets.
template <int MODE, int DUAL>
__global__ __launch_bounds__(512, 1) void proj16_kernel(
    const __half* __restrict__ whiA, const float* __restrict__ biasA,
    const __half* __restrict__ X, __half* __restrict__ outA, float scaleA,
    const __half* __restrict__ whiB, const float* __restrict__ biasB,
    __half* __restrict__ outB, float scaleB)
{
    extern __shared__ char smem[];
    const uint32_t sb = smem_u32(smem);
    const int tid = threadIdx.x;
    const int l = tid & 31;
    const int w = tid >> 5;                 // 0..15
    const int g = l >> 2;
    const int t = l & 3;
    const int n0 = blockIdx.x * 256;
    const int h0 = blockIdx.y * 128;
    const int p  = DUAL ? (blockIdx.z >> 2) : 0;
    const int b  = DUAL ? (blockIdx.z & 3) : blockIdx.z;
    const __half* whi  = (DUAL && p) ? whiB  : whiA;
    const float*  bias = (DUAL && p) ? biasB : biasA;
    __half*       out  = (DUAL && p) ? outB  : outA;
    const float   scale= (DUAL && p) ? scaleB: scaleA;
    const __half* Xb = X + (size_t)b * Cn * Nn;

    float acc[16][4] = {};   // 64 regs

    proj_issue(sb, 0, whi, Xb, h0, n0, 0, tid);
    CP_COMMIT();
    proj_issue(sb, 1, whi, Xb, h0, n0, 32, tid);
    CP_COMMIT();

    if (MODE == 0) {
        // 16 warps: 4(h) x 4(n) -> warp tile 32h x 64n
        const int wh = (w & 3) * 32;
        const int wn = (w >> 2) * 64;
        const uint32_t aW = (uint32_t)((wh + (l & 15)) * 80 + (l >> 4) * 16);
        const uint32_t bX = (uint32_t)((((l >> 3) & 1) * 8 + (l & 7)) * 528 + (wn + (l >> 4) * 8) * 2);

        for (int ck = 0; ck < 8; ck++) {
            if (ck < 6) CP_WAIT1(); else CP_WAIT0();
            __syncthreads();
            if (ck <= 5) { proj_issue(sb, (ck + 2) % 3, whi, Xb, h0, n0, (ck + 2) * 32, tid);
                           CP_COMMIT(); }
            const uint32_t bb = sb + (ck % 3) * PJ_BUF;
            #pragma unroll
            for (int ks = 0; ks < 2; ks++) {
                uint32_t q[4][4];
                #pragma unroll
                for (int jj = 0; jj < 4; jj++)
                    ldm4t(q[jj], bb + PJ_X + bX + ks * 8448 + jj * 32);
                uint32_t a[2][4];
                ldm4(a[0], bb + aW + ks * 32);
                ldm4(a[1], bb + aW + 16 * 80 + ks * 32);
                #pragma unroll
                for (int mi = 0; mi < 2; mi++)
                    #pragma unroll
                    for (int jj = 0; jj < 4; jj++) {
                        mma16816(acc[mi * 8 + jj * 2],     a[mi], q[jj][0], q[jj][1]);
                        mma16816(acc[mi * 8 + jj * 2 + 1], a[mi], q[jj][2], q[jj][3]);
                    }
            }
        }
        // epilogue: out[b][h][n]
        #pragma unroll
        for (int mi = 0; mi < 2; mi++) {
            int h = h0 + wh + mi * 16 + g;
            float bv0 = bias[h];
            float bv1 = bias[h + 8];
            #pragma unroll
            for (int j = 0; j < 8; j++) {
                int n = n0 + wn + j * 8 + 2 * t;
                float* a = acc[mi * 8 + j];
                *(uint32_t*)(out + ((size_t)(b * Hn + h)) * Nn + n) =
                    pack2((a[0] + bv0) * scale, (a[1] + bv0) * scale);
                *(uint32_t*)(out + ((size_t)(b * Hn + h + 8)) * Nn + n) =
                    pack2((a[2] + bv1) * scale, (a[3] + bv1) * scale);
            }
        }
    } else {
        // 16 warps: 4(n) x 4(h) -> warp tile 64n x 32h
        const int wn = (w & 3) * 64;
        const int wh = (w >> 2) * 32;
        const uint32_t aX = (uint32_t)(((l >> 4) * 8 + (l & 7)) * 528 + (wn + ((l >> 3) & 1) * 8) * 2);
        const uint32_t bW = (uint32_t)((wh + ((l >> 4) << 3) + (l & 7)) * 80 + ((l >> 3) & 1) * 16);

        for (int ck = 0; ck < 8; ck++) {
            if (ck < 6) CP_WAIT1(); else CP_WAIT0();
            __syncthreads();
            if (ck <= 5) { proj_issue(sb, (ck + 2) % 3, whi, Xb, h0, n0, (ck + 2) * 32, tid);
                           CP_COMMIT(); }
            const uint32_t bb = sb + (ck % 3) * PJ_BUF;
            #pragma unroll
            for (int ks = 0; ks < 2; ks++) {
                uint32_t a[4][4];
                #pragma unroll
                for (int mi = 0; mi < 4; mi++)
                    ldm4t(a[mi], bb + PJ_X + aX + ks * 8448 + mi * 32);
                #pragma unroll
                for (int jj = 0; jj < 2; jj++) {
                    uint32_t qq[4];
                    ldm4(qq, bb + bW + jj * 1280 + ks * 32);
                    #pragma unroll
                    for (int mi = 0; mi < 4; mi++) {
                        mma16816(acc[mi * 4 + jj * 2],     a[mi], qq[0], qq[1]);
                        mma16816(acc[mi * 4 + jj * 2 + 1], a[mi], qq[2], qq[3]);
                    }
                }
            }
        }
        // epilogue: out[b][n][h]
        // acc[mi*4 + j] <-> h-column group j*8 (j = jj*2 + s, s = n8-half of the
        // MMA output); components [0],[1] = row nr, [2],[3] = row nr+8.
        float bvj[4][2];
        #pragma unroll
        for (int j = 0; j < 4; j++) {
            bvj[j][0] = bias[h0 + wh + j * 8 + 2 * t];
            bvj[j][1] = bias[h0 + wh + j * 8 + 2 * t + 1];
        }
        #pragma unroll
        for (int mi = 0; mi < 4; mi++) {
            int nr = n0 + wn + mi * 16 + g;
            #pragma unroll
            for (int j = 0; j < 4; j++) {
                float* a = acc[mi * 4 + j];
                int hc = h0 + wh + j * 8 + 2 * t;
                *(uint32_t*)(out + ((size_t)(b * Nn + nr)) * Hn + hc) =
                    pack2((a[0] + bvj[j][0]) * scale, (a[1] + bvj[j][1]) * scale);
                *(uint32_t*)(out + ((size_t)(b * Nn + nr + 8)) * Hn + hc) =
                    pack2((a[2] + bvj[j][0]) * scale, (a[3] + bvj[j][1]) * scale);
            }
        }
    }
}

// ---------------------------------------------------------------------------
// Grouped conv1d fp16 (unchanged)
// ---------------------------------------------------------------------------
__global__ __launch_bounds__(256) void gconv16_kernel(
    const float* __restrict__ W2, const float* __restrict__ b2)
{
    __shared__ __half xs[8][536];
    __shared__ float ws[192];
    __shared__ float bs[8];

    const int tid = threadIdx.x;
    const int n0 = blockIdx.x * 512;
    const int gr = blockIdx.y;
    const int b  = blockIdx.z;

    if (tid < 192) ws[tid] = W2[gr * 192 + tid];
    if (tid < 8)   bs[tid] = b2[gr * 8 + tid];

    const __half* in = g_v1h + ((size_t)b * Hn + gr * 8) * Nn;
    for (int idx = tid; idx < 8 * 66; idx += 256) {
        int r = idx / 66, c = idx % 66;
        int gn = n0 - 8 + c * 8;
        if (gn >= 0 && gn + 8 <= Nn) {
            *(uint4*)&xs[r][c * 8] = *(const uint4*)(in + (size_t)r * Nn + gn);
        } else {
            #pragma unroll
            for (int j = 0; j < 8; j++) {
                int n = gn + j;
                xs[r][c * 8 + j] = (n >= 0 && n < Nn) ? in[(size_t)r * Nn + n] : __half(0.f);
            }
        }
    }
    __syncthreads();

    __half* ob = g_v2h + ((size_t)b * Hn + gr * 8) * Nn + n0;
    #pragma unroll
    for (int k = 0; k < 2; k++) {
        int n = tid + k * 256;
        float xm[8], x0[8], xp[8];
        #pragma unroll
        for (int i = 0; i < 8; i++) {
            xm[i] = __half2float(xs[i][8 + n - 1]);
            x0[i] = __half2float(xs[i][8 + n]);
            xp[i] = __half2float(xs[i][8 + n + 1]);
        }
        #pragma unroll
        for (int h = 0; h < 8; h++) {
            float acc = bs[h];
            #pragma unroll
            for (int i = 0; i < 8; i++) {
                acc = fmaf(ws[h * 24 + i * 3 + 0], xm[i], acc);
                acc = fmaf(ws[h * 24 + i * 3 + 1], x0[i], acc);
                acc = fmaf(ws[h * 24 + i * 3 + 2], xp[i], acc);
            }
            ob[(size_t)h * Nn + n] = __float2half_rn(fmaxf(acc, 0.f));
        }
    }
}

// ---------------------------------------------------------------------------
// Fused HMMA attention (unchanged from R12)
// ---------------------------------------------------------------------------
#define OFF_Q   0
#define OFF_K   65536
#define OFF_V   131072
#define OFF_E   196608
#define OFF_CS  229376
#define AT_SMEM 230400
#define KBUF    32768
#define VBUF    32768
#define EBUF    16384
#define EXP_BIAS 5.7707802f   /* 4 * log2(e) */

__device__ __forceinline__ void issue_k(uint32_t sb, int buf, const __half* kb, int n0, int tid) {
    uint32_t kd = sb + OFF_K + buf * KBUF;
    #pragma unroll
    for (int i = 0; i < 8; i++) {
        int ch = tid + i * 256;
        int r = ch >> 5, c = ch & 31;
        CP16(kd + r * 512 + ((c ^ (r & 7)) << 4), kb + (size_t)(n0 + r) * Hn + c * 8);
    }
}
__device__ __forceinline__ void issue_v(uint32_t sb, int buf, const __half* vb, int n0, int tid) {
    uint32_t vd = sb + OFF_V + buf * VBUF;
    #pragma unroll
    for (int i = 0; i < 8; i++) {
        int ch = tid + i * 256;
        int r = ch >> 3, c = ch & 7;
        CP16(vd + r * 128 + ((c ^ (r & 7)) << 4), vb + (size_t)r * Nn + n0 + c * 8);
    }
}

#define GEMM1_BODY(kbase) do {                                              \
    _Pragma("unroll")                                                       \
    for (int ks = 0; ks < 16; ks++) {                                       \
        uint32_t a0[4], a1[4], p[4], q[4];                                  \
        ldm4(a0, qrow + (((ks * 2) ^ mq) << 4));                            \
        ldm4(a1, qrow + 16 * 512 + (((ks * 2) ^ mq) << 4));                 \
        ldm4(p, (kbase) + krow_off + (((ks * 2) ^ mk) << 4));               \
        ldm4(q, (kbase) + krow_off + 16 * 512 + (((ks * 2) ^ mk) << 4));    \
        mma16816(acc1[0], a0, p[0], p[1]);                                  \
        mma16816(acc1[1], a0, p[2], p[3]);                                  \
        mma16816(acc1[2], a0, q[0], q[1]);                                  \
        mma16816(acc1[3], a0, q[2], q[3]);                                  \
        mma16816(acc1[4], a1, p[0], p[1]);                                  \
        mma16816(acc1[5], a1, p[2], p[3]);                                  \
        mma16816(acc1[6], a1, q[0], q[1]);                                  \
        mma16816(acc1[7], a1, q[2], q[3]);                                  \
    } } while (0)

#define EPI_UNIT(ebase, u) do {                                             \
    const int _mt = (u) >> 2, _nt = (u) & 3;                                \
    float* _a = acc1[_mt * 4 + _nt];                                        \
    float e00 = ex2(_a[0] - EXP_BIAS);                                      \
    float e01 = ex2(_a[1] - EXP_BIAS);                                      \
    float e10 = ex2(_a[2] - EXP_BIAS);                                      \
    float e11 = ex2(_a[3] - EXP_BIAS);                                      \
    cs[_mt][0] += e00 + e01;                                                \
    cs[_mt][1] += e10 + e11;                                                \
    const uint32_t _erA = eRow0 + (uint32_t)(_mt * 2048);                   \
    const uint32_t _cof = ((eCh ^ (uint32_t)_nt) << 4);                     \
    *(uint32_t*)(smem + (ebase) + _erA + _cof) = pack2(e00, e01);           \
    *(uint32_t*)(smem + (ebase) + _erA + 1024 + _cof) = pack2(e10, e11);    \
    } while (0)

#define EPI_BODY(ebase) do {                                                \
    EPI_UNIT(ebase, 0); EPI_UNIT(ebase, 1); EPI_UNIT(ebase, 2);             \
    EPI_UNIT(ebase, 3); EPI_UNIT(ebase, 4); EPI_UNIT(ebase, 5);             \
    EPI_UNIT(ebase, 6); EPI_UNIT(ebase, 7); } while (0)

#define G2_CHUNK(ebase, vbase, ks) do {                                     \
    uint32_t af[4][4];                                                      \
    _Pragma("unroll")                                                       \
    for (int mt = 0; mt < 4; mt++)                                          \
        ldm4(af[mt], (ebase) + erow_off + mt * 2048 + ((((ks) * 2) ^ me) << 4)); \
    _Pragma("unroll")                                                       \
    for (int j = 0; j < 4; j++) {                                           \
        uint32_t bbv[4];                                                    \
        ldm4(bbv, (vbase) + vrow_off + j * 2048 + ((((ks) * 2) ^ mv) << 4)); \
        _Pragma("unroll")                                                   \
        for (int mt = 0; mt < 4; mt++) {                                    \
            mma16816(acc2[mt * 8 + j * 2],     af[mt], bbv[0], bbv[1]);     \
            mma16816(acc2[mt * 8 + j * 2 + 1], af[mt], bbv[2], bbv[3]);     \
        }                                                                   \
    } } while (0)

__global__ __launch_bounds__(256, 1)
void attn_kernel(const __half* __restrict__ qt, const __half* __restrict__ kt,
                 const __half* __restrict__ vh, float* __restrict__ out)
{
    extern __shared__ char smem[];
    const int tid  = threadIdx.x;
    const int l    = tid & 31;
    const int w    = tid >> 5;
    const int m0 = blockIdx.x * 128;
    const int b  = blockIdx.y;
    const uint32_t sb = smem_u32(smem);
    const int g = l >> 2;
    const int t = l & 3;

    const int wm1 = (w >> 1) * 32;
    const int wn1 = (w & 1) * 32;
    const int wm2 = (w & 1) * 64;
    const int wo2 = (w >> 1) * 64;

    const __half* kb = kt + (size_t)b * Nn * Hn;
    const __half* vb = vh + (size_t)b * On * Nn;

    #pragma unroll
    for (int i = 0; i < 16; i++) {
        int ch = tid + i * 256;
        int r = ch >> 5, c = ch & 31;
        *(float4*)(smem + OFF_Q + r * 512 + ((c ^ (r & 7)) << 4)) =
            *(const float4*)(qt + ((size_t)(b * Nn + m0 + r)) * Hn + c * 8);
    }
    issue_k(sb, 0, kb, 0, tid);
    issue_v(sb, 0, vb, 0, tid);
    CP_COMMIT();
    issue_k(sb, 1, kb, 64, tid);
    CP_COMMIT();

    const uint32_t qrow = sb + OFF_Q + (uint32_t)((wm1 + (l & 15)) * 512);
    const uint32_t mq   = (uint32_t)(((l >> 4) & 1) ^ (l & 7));
    const uint32_t krow_off = (uint32_t)((wn1 + ((l >> 4) << 3) + (l & 7)) * 512);
    const uint32_t mk   = (uint32_t)(((l >> 3) & 1) ^ (l & 7));
    const uint32_t erow_off = (uint32_t)((wm2 + (l & 15)) * 128);
    const uint32_t me   = (uint32_t)(((l >> 4) & 1) ^ (l & 7));
    const uint32_t vrow_off = (uint32_t)((wo2 + ((l >> 4) << 3) + (l & 7)) * 128);
    const uint32_t mv   = (uint32_t)(((l >> 3) & 1) ^ (l & 7));
    const uint32_t eRow0 = (uint32_t)((wm1 + g) * 128 + 4 * t);
    const uint32_t eCh   = (uint32_t)((wn1 >> 3) ^ g);

    float acc2[32][4] = {};
    float cs[2][2] = {};
    float acc1[8][4];

    CP_WAIT0();
    __syncthreads();
    #pragma unroll
    for (int i = 0; i < 8; i++)
        #pragma unroll
        for (int j = 0; j < 4; j++) acc1[i][j] = 0.f;
    GEMM1_BODY(sb + OFF_K + 0 * KBUF);
    EPI_BODY(OFF_E + 0 * EBUF);
    __syncthreads();

    for (int it = 0; it < 63; it++) {
        issue_v(sb, (it + 1) & 1, vb, (it + 1) * 64, tid);
        if (it + 2 < 64) issue_k(sb, it & 1, kb, (it + 2) * 64, tid);
        CP_COMMIT();

        #pragma unroll
        for (int i = 0; i < 8; i++)
            #pragma unroll
            for (int j = 0; j < 4; j++) acc1[i][j] = 0.f;
        GEMM1_BODY(sb + OFF_K + ((it + 1) & 1) * KBUF);

        {
            const uint32_t e2 = sb + OFF_E + (it & 1) * EBUF;
            const uint32_t v2 = sb + OFF_V + (it & 1) * VBUF;
            const uint32_t eW = OFF_E + ((it + 1) & 1) * EBUF;
            G2_CHUNK(e2, v2, 0); EPI_UNIT(eW, 0); EPI_UNIT(eW, 1);
            G2_CHUNK(e2, v2, 1); EPI_UNIT(eW, 2); EPI_UNIT(eW, 3);
            G2_CHUNK(e2, v2, 2); EPI_UNIT(eW, 4); EPI_UNIT(eW, 5);
            G2_CHUNK(e2, v2, 3); EPI_UNIT(eW, 6); EPI_UNIT(eW, 7);
        }

        CP_WAIT0();
        __syncthreads();
    }

    {
        const uint32_t e2 = sb + OFF_E + 1 * EBUF;
        const uint32_t v2 = sb + OFF_V + 1 * VBUF;
        G2_CHUNK(e2, v2, 0); G2_CHUNK(e2, v2, 1);
        G2_CHUNK(e2, v2, 2); G2_CHUNK(e2, v2, 3);
    }

    float* CS = (float*)(smem + OFF_CS);
    #pragma unroll
    for (int mt = 0; mt < 2; mt++)
        #pragma unroll
        for (int h = 0; h < 2; h++) {
            float v = cs[mt][h];
            v += __shfl_xor_sync(0xFFFFFFFFu, v, 1);
            v += __shfl_xor_sync(0xFFFFFFFFu, v, 2);
            if (t == 0) CS[(w & 1) * 128 + wm1 + mt * 16 + g + h * 8] = v;
        }
    __syncthreads();

    float inv[4][2];
    #pragma unroll
    for (int mt = 0; mt < 4; mt++) {
        int r = wm2 + mt * 16 + g;
        inv[mt][0] = 1.f / (CS[r] + CS[128 + r]);
        inv[mt][1] = 1.f / (CS[r + 8] + CS[128 + r + 8]);
    }

    #pragma unroll
    for (int mt = 0; mt < 4; mt++) {
        const int mcol = wm2 + mt * 16 + g;
        #pragma unroll
        for (int ot = 0; ot < 8; ot++) {
            const int o = wo2 + ot * 8 + 2 * t;
            const float* a = acc2[mt * 8 + ot];
            float* p0 = out + ((size_t)(b * On + o)) * Nn + m0;
            float* p1 = p0 + Nn;
            p0[mcol]     = a[0] * inv[mt][0];
            p1[mcol]     = a[1] * inv[mt][0];
            p0[mcol + 8] = a[2] * inv[mt][1];
            p1[mcol + 8] = a[3] * inv[mt][1];
        }
    }
}

// ---------------------------------------------------------------------------
extern "C" void kernel_launch(void* const* d_in, const int* in_sizes, int n_in,
                              void* d_out, int out_size)
{
    const float* x  = (const float*)d_in[0];
    const float* Wk = (const float*)d_in[1];
    const float* bk = (const float*)d_in[2];
    const float* Wq = (const float*)d_in[3];
    const float* bq = (const float*)d_in[4];
    const float* W1 = (const float*)d_in[5];
    const float* b1 = (const float*)d_in[6];
    const float* W2 = (const float*)d_in[7];
    const float* b2 = (const float*)d_in[8];
    const float* W3 = (const float*)d_in[9];
    const float* b3 = (const float*)d_in[10];
    float* out = (float*)d_out;

    __half *x16, *whi, *ktp, *qtp, *v1h, *v2h, *vhp;
    cudaGetSymbolAddress((void**)&x16, g_x16);
    cudaGetSymbolAddress((void**)&whi, g_whi);
    cudaGetSymbolAddress((void**)&ktp, g_kt);
    cudaGetSymbolAddress((void**)&qtp, g_qt);
    cudaGetSymbolAddress((void**)&v1h, g_v1h);
    cudaGetSymbolAddress((void**)&v2h, g_v2h);
    cudaGetSymbolAddress((void**)&vhp, g_vh);

    cudaFuncSetAttribute(proj16_kernel<0,0>, cudaFuncAttributeMaxDynamicSharedMemorySize, PJ_SMEM);
    cudaFuncSetAttribute(proj16_kernel<1,1>, cudaFuncAttributeMaxDynamicSharedMemorySize, PJ_SMEM);
    cudaFuncSetAttribute(attn_kernel, cudaFuncAttributeMaxDynamicSharedMemorySize, AT_SMEM);

    const float LOG2E = 1.4426950408889634f;
    // launch order fixed so attn is the 6th launch (ncu -s 5 profiles it)
    prep_kernel<<<5120, 256>>>(x, Wk, Wq, W1, W3);
    proj16_kernel<1,1><<<dim3(Nn / 256, Hn / 128, 2 * Bn), 512, PJ_SMEM>>>(
        whi + 0 * 65536, bk, x16, ktp, 1.0f,
        whi + 1 * 65536, bq, qtp, LOG2E);
    proj16_kernel<0,0><<<dim3(Nn / 256, Hn / 128, Bn), 512, PJ_SMEM>>>(
        whi + 2 * 65536, b1, x16, v1h, 1.0f,
        nullptr, nullptr, nullptr, 0.f);
    gconv16_kernel<<<dim3(Nn / 512, 32, Bn), 256>>>(W2, b2);
    proj16_kernel<0,0><<<dim3(Nn / 256, Hn / 128, Bn), 512, PJ_SMEM>>>(
        whi + 3 * 65536, b3, v2h, vhp, 1.0f,
        nullptr, nullptr, nullptr, 0.f);
    attn_kernel<<<dim3(Nn / 128, Bn), 256, AT_SMEM>>>(qtp, ktp, vhp, out);
}